// round 5
// baseline (speedup 1.0000x reference)
#include <cuda_runtime.h>
#include <math.h>
#include <stdint.h>

// ---------------- problem constants ----------------
#define Cc    128
#define Jn    25
#define Tt    120
#define Nb    64
#define NT    7680            // Nb*Tt
#define LS    19              // 1 + KKEEP + 1
#define KKEEP 17
#define DDROP 8
#define NH    4
#define HDIM  32
#define DFF   256
#define M_SP  (NT*LS)         // 145920
#define M_T   (Nb*Jn*Tt)      // 192000 (== NT*Jn)
#define ELEM_OUT ((size_t)Nb*Tt*Jn*Cc)   // 24576000

// ---------------- scratch (device globals; no allocations) ----------------
__device__ float g_A[24576000];   // x_gcn (= res_spatial)
__device__ float g_B[24576000];   // x_sp
__device__ float g_C[73728000];   // qkv (spatial then temporal)
__device__ float g_D[24576000];   // attention head outputs
__device__ float g_E[24576000];   // proj output / scratch Y
__device__ float g_F[24576000];   // x_msa (spatial) / xt + a (temporal)
__device__ float g_G[24576000];   // ffn out (spatial) / xt1 (temporal, post-LN1)
__device__ float g_H[49152000];   // ffn hidden
__device__ float g_I[24576000];   // xt1 + ffn (temporal)
__device__ float g_J[18677760];   // x_slow
__device__ float g_Wt[16384];     // gcn_w[0] transposed
__device__ int   g_keep[NT*KKEEP];
__device__ int   g_drop[NT*DDROP];
__device__ float g_phn[NT*DDROP];
__device__ float g_c2o[NT*(LS-1)];

// ---------------- helpers ----------------
__device__ __forceinline__ float wredsum(float v){
    #pragma unroll
    for (int o=16;o;o>>=1) v += __shfl_xor_sync(0xffffffffu, v, o);
    return v;
}
__device__ __forceinline__ float wredmax(float v){
    #pragma unroll
    for (int o=16;o;o>>=1) v = fmaxf(v, __shfl_xor_sync(0xffffffffu, v, o));
    return v;
}
__device__ __forceinline__ float gelu_f(float x){
    return 0.5f*x*(1.0f+erff(x*0.70710678118654752f));
}
// fast exp for x <= 0 (post max-subtract softmax). ~12 FMA/ALU ops, no MUFU.
__device__ __forceinline__ float fast_exp(float x){
    x = fmaxf(x, -80.f);
    float t = x * 1.4426950408889634f;
    float z = t + 12582912.0f;              // rint via magic number
    int   n = __float_as_int(z) - 0x4B400000;
    float r = z - 12582912.0f;
    float f = t - r;                        // f in [-0.5, 0.5]
    float p = 1.3333558e-3f;
    p = fmaf(p, f, 9.6181292e-3f);
    p = fmaf(p, f, 5.5504109e-2f);
    p = fmaf(p, f, 2.4022651e-1f);
    p = fmaf(p, f, 6.9314718e-1f);
    p = fmaf(p, f, 1.0f);
    return p * __int_as_float((n + 127) << 23);
}
// xt row (n*J+j)*T + t  ->  ntj row (n*T+t)*J + j
__device__ __forceinline__ int remap_row(int m){
    int seq = m / Tt; int t = m - seq*Tt;
    int n = seq / Jn; int j = seq - n*Jn;
    return (n*Tt + t)*Jn + j;
}
__device__ __forceinline__ uint32_t f2tf32(float f){
    uint32_t u; asm("cvt.rna.tf32.f32 %0, %1;" : "=r"(u) : "f"(f)); return u;
}
__device__ __forceinline__ void mma_tf32(float c[4], const uint32_t a[4], const uint32_t b[2]){
    asm volatile("mma.sync.aligned.m16n8k8.row.col.f32.tf32.tf32.f32 "
        "{%0,%1,%2,%3}, {%4,%5,%6,%7}, {%8,%9}, {%0,%1,%2,%3};"
        : "+f"(c[0]), "+f"(c[1]), "+f"(c[2]), "+f"(c[3])
        : "r"(a[0]), "r"(a[1]), "r"(a[2]), "r"(a[3]), "r"(b[0]), "r"(b[1]));
}

// ---------------- TF32 tensor-core GEMM ----------------
// Y[m,n] = act( sum_k norm(X[srcX(m),k]) * W[n,k] + bias[n] )
// optional Y2[m,n] = Y[m,n] + res[srcR(m),n]
// Block tile: 128 rows x 64 cols, K chunked by 128. 4 warps, 32 rows each.
#define SSTRIDE 132
#define TG_SMEM ((128+64)*SSTRIDE*4)
template<int KD,int ACT,bool NORM,bool RMX,bool RMR>
__global__ void __launch_bounds__(128) tgemm(
    const float* __restrict__ X, const float* __restrict__ W,
    const float* __restrict__ bias, float* __restrict__ Y,
    const float* __restrict__ res, float* __restrict__ Y2,
    const float* __restrict__ nw, int nout)
{
    extern __shared__ uint32_t smem_u[];
    uint32_t* sA = smem_u;                 // [128][SSTRIDE]
    uint32_t* sW = smem_u + 128*SSTRIDE;   // [64][SSTRIDE]
    const int tid = threadIdx.x, w = tid>>5, lane = tid&31;
    const int m0 = blockIdx.x*128;
    const int gcb = blockIdx.y*64;

    float acc[2][8][4];
    #pragma unroll
    for (int mt=0;mt<2;mt++)
        #pragma unroll
        for (int nt=0;nt<8;nt++)
            #pragma unroll
            for (int q=0;q<4;q++) acc[mt][nt][q]=0.f;

    for (int kc=0; kc<KD; kc+=128){
        if (kc) __syncthreads();
        for (int r=w; r<128; r+=4){
            int m = m0 + r;
            int sm_ = RMX ? remap_row(m) : m;
            float4 v = ((const float4*)(X + (size_t)sm_*KD + kc))[lane];
            if (NORM){
                float ss = wredsum(v.x*v.x+v.y*v.y+v.z*v.z+v.w*v.w);
                float scl = rsqrtf(ss*(1.0f/KD) + 1e-6f);
                float4 g = ((const float4*)nw)[lane];
                v.x*=scl*g.x; v.y*=scl*g.y; v.z*=scl*g.z; v.w*=scl*g.w;
            }
            uint32_t* dst = sA + r*SSTRIDE + lane*4;
            dst[0]=f2tf32(v.x); dst[1]=f2tf32(v.y); dst[2]=f2tf32(v.z); dst[3]=f2tf32(v.w);
        }
        for (int r=w; r<64; r+=4){
            int n = gcb + r;
            float4 v = ((const float4*)(W + (size_t)n*KD + kc))[lane];
            uint32_t* dst = sW + r*SSTRIDE + lane*4;
            dst[0]=f2tf32(v.x); dst[1]=f2tf32(v.y); dst[2]=f2tf32(v.z); dst[3]=f2tf32(v.w);
        }
        __syncthreads();

        const int rr = lane>>2, cc = lane&3;
        #pragma unroll
        for (int ks=0; ks<16; ks++){
            const int k = ks*8;
            uint32_t a0[4], a1[4], bb[8][2];
            const uint32_t* pa = sA + (w*32 + rr)*SSTRIDE + k + cc;
            a0[0]=pa[0];            a0[1]=pa[8*SSTRIDE];
            a0[2]=pa[4];            a0[3]=pa[8*SSTRIDE+4];
            a1[0]=pa[16*SSTRIDE];   a1[1]=pa[24*SSTRIDE];
            a1[2]=pa[16*SSTRIDE+4]; a1[3]=pa[24*SSTRIDE+4];
            const uint32_t* pb = sW + rr*SSTRIDE + k + cc;
            #pragma unroll
            for (int nt=0;nt<8;nt++){
                bb[nt][0]=pb[nt*8*SSTRIDE]; bb[nt][1]=pb[nt*8*SSTRIDE+4];
            }
            #pragma unroll
            for (int nt=0;nt<8;nt++){
                mma_tf32(acc[0][nt], a0, bb[nt]);
                mma_tf32(acc[1][nt], a1, bb[nt]);
            }
        }
    }

    #pragma unroll
    for (int mt=0;mt<2;mt++){
        int r1 = m0 + w*32 + mt*16 + (lane>>2);
        int r2 = r1 + 8;
        #pragma unroll
        for (int nt=0;nt<8;nt++){
            int col = gcb + nt*8 + 2*(lane&3);
            float bx=0.f, by=0.f;
            if (bias){ bx=bias[col]; by=bias[col+1]; }
            float y0=acc[mt][nt][0]+bx, y1=acc[mt][nt][1]+by;
            float y2=acc[mt][nt][2]+bx, y3=acc[mt][nt][3]+by;
            if (ACT==1){ y0=gelu_f(y0); y1=gelu_f(y1); y2=gelu_f(y2); y3=gelu_f(y3); }
            float2 p1 = make_float2(y0,y1), p2 = make_float2(y2,y3);
            *(float2*)&Y[(size_t)r1*nout + col] = p1;
            *(float2*)&Y[(size_t)r2*nout + col] = p2;
            if (Y2){
                int s1 = RMR ? remap_row(r1) : r1;
                int s2 = RMR ? remap_row(r2) : r2;
                float2 q1 = *(const float2*)&res[(size_t)s1*nout + col];
                float2 q2 = *(const float2*)&res[(size_t)s2*nout + col];
                p1.x+=q1.x; p1.y+=q1.y; p2.x+=q2.x; p2.y+=q2.y;
                *(float2*)&Y2[(size_t)r1*nout + col] = p1;
                *(float2*)&Y2[(size_t)r2*nout + col] = p2;
            }
        }
    }
}

// ---------------- W transpose for the GCN ----------------
__global__ void transpose_k(const float* __restrict__ Win, float* __restrict__ Wt){
    int i = blockIdx.x*128 + threadIdx.x;     // i = d*128 + c
    int d = i >> 7, c = i & 127;
    Wt[i] = Win[c*128 + d];
}

// ---------------- rmsnorm over rows ----------------
__global__ void rms_k(const float* __restrict__ X, const float* __restrict__ g,
                      float* __restrict__ Y){
    int m = blockIdx.x*4 + (threadIdx.x>>5);
    int lane = threadIdx.x&31;
    float4 v = ((const float4*)(X + (size_t)m*Cc))[lane];
    float ss = wredsum(v.x*v.x+v.y*v.y+v.z*v.z+v.w*v.w);
    float scl = rsqrtf(ss*(1.0f/Cc) + 1e-6f);
    float4 gg = ((const float4*)g)[lane];
    float4 o = make_float4(v.x*scl*gg.x, v.y*scl*gg.y, v.z*scl*gg.z, v.w*scl*gg.w);
    ((float4*)(Y + (size_t)m*Cc))[lane] = o;
}

// ---------------- per-row sort + drop-softmax ----------------
__global__ void sort_k(const float* __restrict__ sc, int* __restrict__ keep,
                       int* __restrict__ drop, float* __restrict__ phn){
    int r = blockIdx.x*blockDim.x + threadIdx.x;
    if (r >= NT) return;
    float s[Jn]; int id[Jn];
    #pragma unroll
    for (int j=0;j<Jn;j++){ s[j]=sc[r*Jn+j]; id[j]=j; }
    for (int i=1;i<Jn;i++){
        float sv=s[i]; int iv=id[i]; int p=i-1;
        while (p>=0 && s[p] < sv){ s[p+1]=s[p]; id[p+1]=id[p]; p--; }
        s[p+1]=sv; id[p+1]=iv;
    }
    #pragma unroll
    for (int p=0;p<KKEEP;p++) keep[r*KKEEP+p]=id[p];
    float mx = -1e30f;
    #pragma unroll
    for (int p=0;p<DDROP;p++) mx = fmaxf(mx, s[KKEEP+p]);
    float e[DDROP]; float sum=0.f;
    #pragma unroll
    for (int p=0;p<DDROP;p++){ e[p]=expf(s[KKEEP+p]-mx); sum+=e[p]; }
    float inv = 1.f/sum;
    #pragma unroll
    for (int p=0;p<DDROP;p++){ drop[r*DDROP+p]=id[KKEEP+p]; phn[r*DDROP+p]=e[p]*inv; }
}

// ---------------- build x_slow ----------------
__global__ void build_slow_k(const float* __restrict__ xgcn, const float* __restrict__ cls,
                             const int* __restrict__ keep, const int* __restrict__ drop,
                             const float* __restrict__ phn, float* __restrict__ xslow){
    int nt = blockIdx.x; int c = threadIdx.x;
    size_t ob = (size_t)nt*LS*Cc;
    xslow[ob + c] = cls[c];
    #pragma unroll
    for (int p=0;p<KKEEP;p++){
        int j = keep[nt*KKEEP+p];
        xslow[ob + (size_t)(1+p)*Cc + c] = xgcn[((size_t)nt*Jn + j)*Cc + c];
    }
    float acc = 0.f;
    #pragma unroll
    for (int p=0;p<DDROP;p++){
        int j = drop[nt*DDROP+p];
        acc = fmaf(phn[nt*DDROP+p], xgcn[((size_t)nt*Jn + j)*Cc + c], acc);
    }
    xslow[ob + (size_t)(LS-1)*Cc + c] = acc;
}

// ---------------- spatial attention (L=19, 4 heads, warp per head) ----------------
__global__ void attn_s_k(const float* __restrict__ qkv, float* __restrict__ ao,
                         float* __restrict__ c2o){
    __shared__ float sq[NH][LS][HDIM];
    __shared__ float sv[NH][LS][HDIM];
    __shared__ float sp[NH][32];
    __shared__ float sc2[NH][LS-1];
    int nt = blockIdx.x; int tid = threadIdx.x; int h = tid>>5, lane = tid&31;
    const float* base = qkv + (size_t)nt*LS*384;
    for (int i=0;i<LS;i++){
        sq[h][i][lane] = base[i*384 + h*32 + lane]*0.176776695296637f; // 1/sqrt(32)
        sv[h][i][lane] = base[i*384 + 256 + h*32 + lane];
    }
    float4 kr[8];
    if (lane < LS){
        const float4* kp = (const float4*)(base + lane*384 + 128 + h*32);
        #pragma unroll
        for (int q=0;q<8;q++) kr[q]=kp[q];
    }
    __syncwarp();
    for (int i=0;i<LS;i++){
        float s = -1e30f;
        if (lane < LS){
            s = 0.f;
            const float4* qp = (const float4*)sq[h][i];
            #pragma unroll
            for (int q=0;q<8;q++){
                float4 a = qp[q];
                s = fmaf(a.x,kr[q].x,fmaf(a.y,kr[q].y,fmaf(a.z,kr[q].z,fmaf(a.w,kr[q].w,s))));
            }
        }
        float mx = wredmax(s);
        float e = (lane < LS) ? fast_exp(s-mx) : 0.f;
        float sum = wredsum(e);
        float p = e/sum;
        sp[h][lane] = p;
        __syncwarp();
        if (i==0 && lane>=1 && lane<LS) sc2[h][lane-1] = p;
        float o = 0.f;
        #pragma unroll
        for (int j=0;j<LS;j++) o = fmaf(sp[h][j], sv[h][j][lane], o);
        ao[((size_t)nt*LS + i)*Cc + h*32 + lane] = o;
        __syncwarp();
    }
    __syncthreads();
    if (tid < LS-1)
        c2o[(size_t)nt*(LS-1)+tid] = 0.25f*(sc2[0][tid]+sc2[1][tid]+sc2[2][tid]+sc2[3][tid]);
}

// ---------------- temporal attention, TF32 tensor cores ----------------
// Block = (seq, head), 256 threads (8 warps). Warp w owns score rows w*16..w*16+15.
#define ATT_SMEM ((2*128*36 + 128*132 + 32*132)*4)
__global__ void __launch_bounds__(256) attn_t_tc(const float* __restrict__ qkv,
                                                 float* __restrict__ ao){
    extern __shared__ uint32_t sm[];
    uint32_t* sQ = sm;                       // [128][36] tf32 (rows>=120 zero)
    uint32_t* sK = sm + 128*36;              // [128][36] tf32 (rows>=120 zero)
    uint32_t* sS = sm + 2*128*36;            // [128][132] scores f32 -> probs tf32
    uint32_t* sV = sm + 2*128*36 + 128*132;  // [32][132]  V^T tf32 (cols>=120 zero)
    int seq = blockIdx.x, h = blockIdx.y;
    int tid = threadIdx.x, w = tid>>5, lane = tid&31;
    const int rr = lane>>2, cc = lane&3;
    const float* base = qkv + (size_t)seq*Tt*384 + h*32;

    // stage Q (pre-scaled), K, V^T as tf32, zero-padded to 128 tokens
    for (int idx = tid; idx < 128*32; idx += 256){
        int j = idx>>5, d = idx&31;
        float qv=0.f, kv=0.f, vv=0.f;
        if (j < Tt){
            const float* rp = base + (size_t)j*384;
            qv = rp[d]*0.176776695296637f;
            kv = rp[128+d];
            vv = rp[256+d];
        }
        sQ[j*36+d] = f2tf32(qv);
        sK[j*36+d] = f2tf32(kv);
        sV[d*132+j] = f2tf32(vv);
    }
    __syncthreads();

    // S = Q K^T : warp w -> rows [w*16, w*16+16) x cols [0,128)
    {
        float acc[16][4];
        #pragma unroll
        for (int nt=0;nt<16;nt++){ acc[nt][0]=0.f; acc[nt][1]=0.f; acc[nt][2]=0.f; acc[nt][3]=0.f; }
        #pragma unroll
        for (int ks=0; ks<4; ks++){
            const int k = ks*8;
            uint32_t a[4];
            const uint32_t* pa = sQ + (w*16+rr)*36 + k + cc;
            a[0]=pa[0]; a[1]=pa[8*36]; a[2]=pa[4]; a[3]=pa[8*36+4];
            #pragma unroll
            for (int nt=0; nt<16; nt++){
                const uint32_t* pb = sK + (nt*8+rr)*36 + k + cc;
                uint32_t b[2] = {pb[0], pb[4]};
                mma_tf32(acc[nt], a, b);
            }
        }
        int r1 = w*16 + rr;
        #pragma unroll
        for (int nt=0; nt<16; nt++){
            int col = nt*8 + 2*cc;
            *(float2*)(sS + r1*132 + col)     = make_float2(acc[nt][0], acc[nt][1]);
            *(float2*)(sS + (r1+8)*132 + col) = make_float2(acc[nt][2], acc[nt][3]);
        }
    }
    __syncwarp();

    // softmax on own rows (valid cols < 120); write probs back as tf32, zero cols 120..127
    for (int s=0; s<16; s++){
        int row = w*16 + s;
        if (row >= Tt) break;
        float* rs = (float*)(sS + row*132);
        float v0 = rs[lane], v1 = rs[lane+32], v2 = rs[lane+64];
        float v3 = (lane<24) ? rs[lane+96] : -1e30f;
        float mx = wredmax(fmaxf(fmaxf(v0,v1), fmaxf(v2,v3)));
        float e0=fast_exp(v0-mx), e1=fast_exp(v1-mx), e2=fast_exp(v2-mx);
        float e3=(lane<24)?fast_exp(v3-mx):0.f;
        float inv = 1.f/wredsum(e0+e1+e2+e3);
        uint32_t* ru = sS + row*132;
        ru[lane]    = f2tf32(e0*inv);
        ru[lane+32] = f2tf32(e1*inv);
        ru[lane+64] = f2tf32(e2*inv);
        ru[lane+96] = (lane<24) ? f2tf32(e3*inv) : 0u;
    }
    __syncwarp();

    // O = P V : rows w*16.., cols 0..31 (head dims)
    {
        float acc[4][4];
        #pragma unroll
        for (int nt=0;nt<4;nt++){ acc[nt][0]=0.f; acc[nt][1]=0.f; acc[nt][2]=0.f; acc[nt][3]=0.f; }
        #pragma unroll
        for (int ks=0; ks<16; ks++){
            const int k = ks*8;
            uint32_t a[4];
            const uint32_t* pa = sS + (w*16+rr)*132 + k + cc;
            a[0]=pa[0]; a[1]=pa[8*132]; a[2]=pa[4]; a[3]=pa[8*132+4];
            #pragma unroll
            for (int nt=0; nt<4; nt++){
                const uint32_t* pb = sV + (nt*8+rr)*132 + k + cc;
                uint32_t b[2] = {pb[0], pb[4]};
                mma_tf32(acc[nt], a, b);
            }
        }
        int r1 = w*16 + rr;
        #pragma unroll
        for (int nt=0; nt<4; nt++){
            int col = nt*8 + 2*cc;
            if (r1 < Tt)
                *(float2*)&ao[((size_t)seq*Tt + r1)*Cc + h*32 + col] = make_float2(acc[nt][0], acc[nt][1]);
            if (r1+8 < Tt)
                *(float2*)&ao[((size_t)seq*Tt + r1+8)*Cc + h*32 + col] = make_float2(acc[nt][2], acc[nt][3]);
        }
    }
}

// ---------------- spatial scatter + next_attn ----------------
__global__ void scatter_k(const float* __restrict__ xgcn, const float* __restrict__ xmsa,
                          const float* __restrict__ ffn, const float* __restrict__ attnout,
                          const int* __restrict__ keep, const int* __restrict__ drop,
                          const float* __restrict__ c2o, float* __restrict__ xsp,
                          float* __restrict__ nextattn){
    int nt = blockIdx.x; int c = threadIdx.x;
    size_t sb = (size_t)nt*LS*Cc;
    float rep = attnout[sb + (size_t)(LS-1)*Cc + c] + ffn[sb + (size_t)(LS-1)*Cc + c];
    #pragma unroll
    for (int p=0;p<KKEEP;p++){
        int j = keep[nt*KKEEP+p];
        size_t o = ((size_t)nt*Jn + j)*Cc + c;
        xsp[o] = xgcn[o] + xmsa[sb + (size_t)(1+p)*Cc + c] + ffn[sb + (size_t)(1+p)*Cc + c];
    }
    #pragma unroll
    for (int p=0;p<DDROP;p++){
        int j = drop[nt*DDROP+p];
        size_t o = ((size_t)nt*Jn + j)*Cc + c;
        xsp[o] = 2.f*xgcn[o] + rep;
    }
    if (c < KKEEP)
        nextattn[(size_t)nt*Jn + keep[nt*KKEEP+c]] = c2o[nt*(LS-1)+c];
    else if (c < Jn)
        nextattn[(size_t)nt*Jn + drop[nt*DDROP + (c-KKEEP)]] = c2o[nt*(LS-1)+KKEEP];
}

// ---------------- layernorm (temporal LN1) ----------------
__global__ void ln_k(const float* __restrict__ X, const float* __restrict__ w,
                     const float* __restrict__ b, float* __restrict__ Y){
    int m = blockIdx.x*4 + (threadIdx.x>>5);
    int lane = threadIdx.x&31;
    const float4* xp = (const float4*)(X + (size_t)m*Cc);
    float4 v = xp[lane];
    float mean = wredsum(v.x+v.y+v.z+v.w)*(1.0f/Cc);
    float d0=v.x-mean, d1=v.y-mean, d2=v.z-mean, d3=v.w-mean;
    float var = wredsum(d0*d0+d1*d1+d2*d2+d3*d3)*(1.0f/Cc);
    float inv = rsqrtf(var + 1e-5f);
    float4 wv = ((const float4*)w)[lane];
    float4 bv = ((const float4*)b)[lane];
    float4 o = make_float4(d0*inv*wv.x+bv.x, d1*inv*wv.y+bv.y, d2*inv*wv.z+bv.z, d3*inv*wv.w+bv.w);
    ((float4*)(Y + (size_t)m*Cc))[lane] = o;
}

// ---------------- final: LN2 + rmsnorm + transpose-back + residuals ----------------
__global__ void final_k(const float* __restrict__ Xi, const float* __restrict__ w,
                        const float* __restrict__ b, const float* __restrict__ tnw,
                        const float* __restrict__ xsp, const float* __restrict__ xin,
                        float* __restrict__ out){
    int m = blockIdx.x*4 + (threadIdx.x>>5);
    int lane = threadIdx.x&31;
    const float4* xp = (const float4*)(Xi + (size_t)m*Cc);
    float4 v = xp[lane];
    float mean = wredsum(v.x+v.y+v.z+v.w)*(1.0f/Cc);
    float d0=v.x-mean, d1=v.y-mean, d2=v.z-mean, d3=v.w-mean;
    float var = wredsum(d0*d0+d1*d1+d2*d2+d3*d3)*(1.0f/Cc);
    float inv = rsqrtf(var + 1e-5f);
    float4 wv = ((const float4*)w)[lane];
    float4 bv = ((const float4*)b)[lane];
    float z0 = d0*inv*wv.x+bv.x, z1 = d1*inv*wv.y+bv.y, z2 = d2*inv*wv.z+bv.z, z3 = d3*inv*wv.w+bv.w;
    float ss = wredsum(z0*z0+z1*z1+z2*z2+z3*z3);
    float rs = rsqrtf(ss*(1.0f/Cc) + 1e-6f);
    float4 tv = ((const float4*)tnw)[lane];
    z0 *= rs*tv.x; z1 *= rs*tv.y; z2 *= rs*tv.z; z3 *= rs*tv.w;
    int dst = remap_row(m);
    float4 a = ((const float4*)(xsp + (size_t)dst*Cc))[lane];
    float4 c = ((const float4*)(xin + (size_t)dst*Cc))[lane];
    float4 o = make_float4(z0+a.x+c.x, z1+a.y+c.y, z2+a.z+c.z, z3+a.w+c.w);
    ((float4*)(out + (size_t)dst*Cc))[lane] = o;
}

// ---------------- host launch ----------------
extern "C" void kernel_launch(void* const* d_in, const int* in_sizes, int n_in,
                              void* d_out, int out_size){
    const float* x      = (const float*)d_in[0];
    const float* scores = (const float*)d_in[1];
    const float* gcn_w  = (const float*)d_in[2];
    const float* gnw    = (const float*)d_in[3];
    const float* cls    = (const float*)d_in[4];
    const float* sn1w   = (const float*)d_in[5];
    const float* sn2w   = (const float*)d_in[6];
    const float* s_inw  = (const float*)d_in[7];
    const float* s_inb  = (const float*)d_in[8];
    const float* s_ow   = (const float*)d_in[9];
    const float* s_ob   = (const float*)d_in[10];
    const float* s_f1w  = (const float*)d_in[11];
    const float* s_f1b  = (const float*)d_in[12];
    const float* s_f2w  = (const float*)d_in[13];
    const float* s_f2b  = (const float*)d_in[14];
    const float* t_inw  = (const float*)d_in[15];
    const float* t_inb  = (const float*)d_in[16];
    const float* t_ow   = (const float*)d_in[17];
    const float* t_ob   = (const float*)d_in[18];
    const float* t_l1w  = (const float*)d_in[19];
    const float* t_l1b  = (const float*)d_in[20];
    const float* t_l2w  = (const float*)d_in[21];
    const float* t_l2b  = (const float*)d_in[22];
    const float* t_f1w  = (const float*)d_in[23];
    const float* t_f1b  = (const float*)d_in[24];
    const float* t_f2w  = (const float*)d_in[25];
    const float* t_f2b  = (const float*)d_in[26];
    const float* tnw    = (const float*)d_in[27];
    float* out = (float*)d_out;
    float* out_attn = out + ((size_t)out_size - (size_t)NT*Jn);

    float *A,*B,*Cq,*D,*E,*F,*G,*Hh,*Ii,*Jb,*Wt,*PHN,*C2O;
    int *KEEP,*DROP;
    cudaGetSymbolAddress((void**)&A,  g_A);
    cudaGetSymbolAddress((void**)&B,  g_B);
    cudaGetSymbolAddress((void**)&Cq, g_C);
    cudaGetSymbolAddress((void**)&D,  g_D);
    cudaGetSymbolAddress((void**)&E,  g_E);
    cudaGetSymbolAddress((void**)&F,  g_F);
    cudaGetSymbolAddress((void**)&G,  g_G);
    cudaGetSymbolAddress((void**)&Hh, g_H);
    cudaGetSymbolAddress((void**)&Ii, g_I);
    cudaGetSymbolAddress((void**)&Jb, g_J);
    cudaGetSymbolAddress((void**)&Wt, g_Wt);
    cudaGetSymbolAddress((void**)&KEEP, g_keep);
    cudaGetSymbolAddress((void**)&DROP, g_drop);
    cudaGetSymbolAddress((void**)&PHN, g_phn);
    cudaGetSymbolAddress((void**)&C2O, g_c2o);

    cudaFuncSetAttribute(tgemm<128,0,false,false,false>, cudaFuncAttributeMaxDynamicSharedMemorySize, TG_SMEM);
    cudaFuncSetAttribute(tgemm<128,0,true, false,false>, cudaFuncAttributeMaxDynamicSharedMemorySize, TG_SMEM);
    cudaFuncSetAttribute(tgemm<128,1,true, false,false>, cudaFuncAttributeMaxDynamicSharedMemorySize, TG_SMEM);
    cudaFuncSetAttribute(tgemm<128,1,false,false,false>, cudaFuncAttributeMaxDynamicSharedMemorySize, TG_SMEM);
    cudaFuncSetAttribute(tgemm<256,0,false,false,false>, cudaFuncAttributeMaxDynamicSharedMemorySize, TG_SMEM);
    cudaFuncSetAttribute(tgemm<128,0,false,true, false>, cudaFuncAttributeMaxDynamicSharedMemorySize, TG_SMEM);
    cudaFuncSetAttribute(tgemm<128,0,false,false,true >, cudaFuncAttributeMaxDynamicSharedMemorySize, TG_SMEM);
    cudaFuncSetAttribute(attn_t_tc, cudaFuncAttributeMaxDynamicSharedMemorySize, ATT_SMEM);

    // 1) transpose gcn_w[0]; 2) sort scores
    transpose_k<<<128,128>>>(gcn_w, Wt);
    sort_k<<<NT/128,128>>>(scores, KEEP, DROP, PHN);

    // 3) GCN: E = x @ W0^T ; then A = rmsnorm(E)*gnw
    tgemm<128,0,false,false,false><<<dim3(M_T/128,2),128,TG_SMEM>>>(x, Wt, nullptr, E, nullptr, nullptr, nullptr, 128);
    rms_k<<<M_T/4,128>>>(E, gnw, A);

    // 4) build x_slow
    build_slow_k<<<NT,128>>>(A, cls, KEEP, DROP, PHN, Jb);

    // 5) spatial QKV = rmsnorm(x_slow, sn1) @ s_inw^T + b
    tgemm<128,0,true,false,false><<<dim3(M_SP/128,6),128,TG_SMEM>>>(Jb, s_inw, s_inb, Cq, nullptr, nullptr, sn1w, 384);

    // 6) spatial attention -> D, C2O
    attn_s_k<<<NT,128>>>(Cq, D, C2O);

    // 7) out-proj: E = attn_out ; F = x_slow + attn_out (x_msa)
    tgemm<128,0,false,false,false><<<dim3(M_SP/128,2),128,TG_SMEM>>>(D, s_ow, s_ob, E, Jb, F, nullptr, 128);

    // 8) FFN1: H = gelu(rmsnorm(x_msa, sn2) @ s_f1w^T + b)
    tgemm<128,1,true,false,false><<<dim3(M_SP/128,4),128,TG_SMEM>>>(F, s_f1w, s_f1b, Hh, nullptr, nullptr, sn2w, 256);

    // 9) FFN2: G = H @ s_f2w^T + b
    tgemm<256,0,false,false,false><<<dim3(M_SP/128,2),128,TG_SMEM>>>(Hh, s_f2w, s_f2b, G, nullptr, nullptr, nullptr, 128);

    // 10) scatter -> B (x_sp), next_attn
    scatter_k<<<NT,128>>>(A, F, G, E, KEEP, DROP, C2O, B, out_attn);

    // 11) temporal QKV (row-remapped transpose fused)
    tgemm<128,0,false,true,false><<<dim3(M_T/128,6),128,TG_SMEM>>>(B, t_inw, t_inb, Cq, nullptr, nullptr, nullptr, 384);

    // 12) temporal attention (tensor cores) -> D
    attn_t_tc<<<dim3(Nb*Jn, NH), 256, ATT_SMEM>>>(Cq, D);

    // 13) out-proj: F = xt + a  (residual remapped from x_sp)
    tgemm<128,0,false,false,true><<<dim3(M_T/128,2),128,TG_SMEM>>>(D, t_ow, t_ob, E, B, F, nullptr, 128);

    // 14) LN1: G = layernorm(F)
    ln_k<<<M_T/4,128>>>(F, t_l1w, t_l1b, G);

    // 15) FFN1: H = gelu(G @ t_f1w^T + b)
    tgemm<128,1,false,false,false><<<dim3(M_T/128,4),128,TG_SMEM>>>(G, t_f1w, t_f1b, Hh, nullptr, nullptr, nullptr, 256);

    // 16) FFN2: I = xt1 + (H @ t_f2w^T + b)
    tgemm<256,0,false,false,false><<<dim3(M_T/128,2),128,TG_SMEM>>>(Hh, t_f2w, t_f2b, E, G, Ii, nullptr, 128);

    // 17) LN2 + rmsnorm + transpose back + residuals -> out
    final_k<<<M_T/4,128>>>(Ii, t_l2w, t_l2b, tnw, B, x, out);
}

// round 7
// speedup vs baseline: 1.5168x; 1.5168x over previous
#include <cuda_runtime.h>
#include <math.h>
#include <stdint.h>

// ---------------- problem constants ----------------
#define Cc    128
#define Jn    25
#define Tt    120
#define Nb    64
#define NT    7680            // Nb*Tt
#define LS    19              // 1 + KKEEP + 1
#define KKEEP 17
#define DDROP 8
#define NH    4
#define HDIM  32
#define DFF   256
#define M_SP  (NT*LS)         // 145920
#define M_T   (Nb*Jn*Tt)      // 192000 (== NT*Jn)
#define ELEM_OUT ((size_t)Nb*Tt*Jn*Cc)   // 24576000

// ---------------- scratch (device globals; no allocations) ----------------
__device__ float g_A[24576000];   // x_gcn (= res_spatial)
__device__ float g_B[24576000];   // x_sp
__device__ float g_C[73728000];   // qkv (spatial then temporal)
__device__ float g_D[24576000];   // attention head outputs
__device__ float g_E[24576000];   // proj output / scratch Y
__device__ float g_F[24576000];   // x_msa (spatial) / xt + a (temporal)
__device__ float g_G[24576000];   // ffn out (spatial) / xt1 (temporal, post-LN1)
__device__ float g_H[49152000];   // ffn hidden
__device__ float g_I[24576000];   // xt1 + ffn (temporal)
__device__ float g_J[18677760];   // x_slow
__device__ float g_Wt[16384];     // gcn_w[0] transposed
__device__ int   g_keep[NT*KKEEP];
__device__ int   g_drop[NT*DDROP];
__device__ float g_phn[NT*DDROP];
__device__ float g_c2o[NT*(LS-1)];

// ---------------- helpers ----------------
__device__ __forceinline__ float wredsum(float v){
    #pragma unroll
    for (int o=16;o;o>>=1) v += __shfl_xor_sync(0xffffffffu, v, o);
    return v;
}
__device__ __forceinline__ float wredmax(float v){
    #pragma unroll
    for (int o=16;o;o>>=1) v = fmaxf(v, __shfl_xor_sync(0xffffffffu, v, o));
    return v;
}
__device__ __forceinline__ float gelu_f(float x){
    return 0.5f*x*(1.0f+erff(x*0.70710678118654752f));
}
// fast exp (FMA-only, no MUFU). Accurate to ~2e-6 rel for softmax-range args.
__device__ __forceinline__ float fast_exp(float x){
    x = fmaxf(x, -80.f);
    float t = x * 1.4426950408889634f;
    float z = t + 12582912.0f;              // rint via magic number
    int   n = __float_as_int(z) - 0x4B400000;
    float r = z - 12582912.0f;
    float f = t - r;                        // f in [-0.5, 0.5]
    float p = 1.3333558e-3f;
    p = fmaf(p, f, 9.6181292e-3f);
    p = fmaf(p, f, 5.5504109e-2f);
    p = fmaf(p, f, 2.4022651e-1f);
    p = fmaf(p, f, 6.9314718e-1f);
    p = fmaf(p, f, 1.0f);
    return p * __int_as_float((n + 127) << 23);
}
// xt row (n*J+j)*T + t  ->  ntj row (n*T+t)*J + j
__device__ __forceinline__ int remap_row(int m){
    int seq = m / Tt; int t = m - seq*Tt;
    int n = seq / Jn; int j = seq - n*Jn;
    return (n*Tt + t)*Jn + j;
}
__device__ __forceinline__ uint32_t f2tf32(float f){
    uint32_t u; asm("cvt.rna.tf32.f32 %0, %1;" : "=r"(u) : "f"(f)); return u;
}
__device__ __forceinline__ void mma_tf32(float c[4], const uint32_t a[4], const uint32_t b[2]){
    asm volatile("mma.sync.aligned.m16n8k8.row.col.f32.tf32.tf32.f32 "
        "{%0,%1,%2,%3}, {%4,%5,%6,%7}, {%8,%9}, {%0,%1,%2,%3};"
        : "+f"(c[0]), "+f"(c[1]), "+f"(c[2]), "+f"(c[3])
        : "r"(a[0]), "r"(a[1]), "r"(a[2]), "r"(a[3]), "r"(b[0]), "r"(b[1]));
}

// ---------------- TF32 tensor-core GEMM ----------------
// Y[m,n] = act( sum_k norm(X[srcX(m),k]) * W[n,k] + bias[n] )
// optional Y2[m,n] = Y[m,n] + res[srcR(m),n]
// Block: 128 rows; loops over NOUT in 64-col groups (X staged once when KD==128).
#define SSTRIDE 132
#define TG_SMEM ((128+64)*SSTRIDE*4)
template<int KD,int NOUT,int ACT,bool NORM,bool RMX,bool RMR>
__global__ void __launch_bounds__(128) tgemm(
    const float* __restrict__ X, const float* __restrict__ W,
    const float* __restrict__ bias, float* __restrict__ Y,
    const float* __restrict__ res, float* __restrict__ Y2,
    const float* __restrict__ nw)
{
    extern __shared__ uint32_t smem_u[];
    uint32_t* sA = smem_u;                 // [128][SSTRIDE]
    uint32_t* sW = smem_u + 128*SSTRIDE;   // [64][SSTRIDE]
    const int tid = threadIdx.x, w = tid>>5, lane = tid&31;
    const int m0 = blockIdx.x*128;
    const int rr = lane>>2, cc = lane&3;
    constexpr int NCG = NOUT/64;

    #pragma unroll 1
    for (int cg=0; cg<NCG; cg++){
        const int gcb = cg*64;
        float acc[2][8][4];
        #pragma unroll
        for (int mt=0;mt<2;mt++)
            #pragma unroll
            for (int nt=0;nt<8;nt++)
                #pragma unroll
                for (int q=0;q<4;q++) acc[mt][nt][q]=0.f;

        #pragma unroll 1
        for (int kc=0; kc<KD; kc+=128){
            if (cg || kc) __syncthreads();   // protect smem reuse
            if (cg==0 || KD>128){
                for (int r=w; r<128; r+=4){
                    int m = m0 + r;
                    int sm_ = RMX ? remap_row(m) : m;
                    float4 v = ((const float4*)(X + (size_t)sm_*KD + kc))[lane];
                    if (NORM){
                        float ss = wredsum(v.x*v.x+v.y*v.y+v.z*v.z+v.w*v.w);
                        float scl = rsqrtf(ss*(1.0f/KD) + 1e-6f);
                        float4 g = ((const float4*)nw)[lane];
                        v.x*=scl*g.x; v.y*=scl*g.y; v.z*=scl*g.z; v.w*=scl*g.w;
                    }
                    uint32_t* dst = sA + r*SSTRIDE + lane*4;
                    dst[0]=f2tf32(v.x); dst[1]=f2tf32(v.y); dst[2]=f2tf32(v.z); dst[3]=f2tf32(v.w);
                }
            }
            for (int r=w; r<64; r+=4){
                int n = gcb + r;
                float4 v = ((const float4*)(W + (size_t)n*KD + kc))[lane];
                uint32_t* dst = sW + r*SSTRIDE + lane*4;
                dst[0]=f2tf32(v.x); dst[1]=f2tf32(v.y); dst[2]=f2tf32(v.z); dst[3]=f2tf32(v.w);
            }
            __syncthreads();

            #pragma unroll
            for (int ks=0; ks<16; ks++){
                const int k = ks*8;
                uint32_t a0[4], a1[4], bb[8][2];
                const uint32_t* pa = sA + (w*32 + rr)*SSTRIDE + k + cc;
                a0[0]=pa[0];            a0[1]=pa[8*SSTRIDE];
                a0[2]=pa[4];            a0[3]=pa[8*SSTRIDE+4];
                a1[0]=pa[16*SSTRIDE];   a1[1]=pa[24*SSTRIDE];
                a1[2]=pa[16*SSTRIDE+4]; a1[3]=pa[24*SSTRIDE+4];
                const uint32_t* pb = sW + rr*SSTRIDE + k + cc;
                #pragma unroll
                for (int nt=0;nt<8;nt++){
                    bb[nt][0]=pb[nt*8*SSTRIDE]; bb[nt][1]=pb[nt*8*SSTRIDE+4];
                }
                #pragma unroll
                for (int nt=0;nt<8;nt++){
                    mma_tf32(acc[0][nt], a0, bb[nt]);
                    mma_tf32(acc[1][nt], a1, bb[nt]);
                }
            }
        }

        // epilogue for this column group
        #pragma unroll
        for (int mt=0;mt<2;mt++){
            int r1 = m0 + w*32 + mt*16 + rr;
            int r2 = r1 + 8;
            #pragma unroll
            for (int nt=0;nt<8;nt++){
                int col = gcb + nt*8 + 2*cc;
                float bx=0.f, by=0.f;
                if (bias){ bx=bias[col]; by=bias[col+1]; }
                float y0=acc[mt][nt][0]+bx, y1=acc[mt][nt][1]+by;
                float y2=acc[mt][nt][2]+bx, y3=acc[mt][nt][3]+by;
                if (ACT==1){ y0=gelu_f(y0); y1=gelu_f(y1); y2=gelu_f(y2); y3=gelu_f(y3); }
                float2 p1 = make_float2(y0,y1), p2 = make_float2(y2,y3);
                *(float2*)&Y[(size_t)r1*NOUT + col] = p1;
                *(float2*)&Y[(size_t)r2*NOUT + col] = p2;
                if (Y2){
                    int s1 = RMR ? remap_row(r1) : r1;
                    int s2 = RMR ? remap_row(r2) : r2;
                    float2 q1 = *(const float2*)&res[(size_t)s1*NOUT + col];
                    float2 q2 = *(const float2*)&res[(size_t)s2*NOUT + col];
                    p1.x+=q1.x; p1.y+=q1.y; p2.x+=q2.x; p2.y+=q2.y;
                    *(float2*)&Y2[(size_t)r1*NOUT + col] = p1;
                    *(float2*)&Y2[(size_t)r2*NOUT + col] = p2;
                }
            }
        }
    }
}

// ---------------- W transpose for the GCN ----------------
__global__ void transpose_k(const float* __restrict__ Win, float* __restrict__ Wt){
    int i = blockIdx.x*128 + threadIdx.x;     // i = d*128 + c
    int d = i >> 7, c = i & 127;
    Wt[i] = Win[c*128 + d];
}

// ---------------- rmsnorm over rows ----------------
__global__ void rms_k(const float* __restrict__ X, const float* __restrict__ g,
                      float* __restrict__ Y){
    int m = blockIdx.x*4 + (threadIdx.x>>5);
    int lane = threadIdx.x&31;
    float4 v = ((const float4*)(X + (size_t)m*Cc))[lane];
    float ss = wredsum(v.x*v.x+v.y*v.y+v.z*v.z+v.w*v.w);
    float scl = rsqrtf(ss*(1.0f/Cc) + 1e-6f);
    float4 gg = ((const float4*)g)[lane];
    float4 o = make_float4(v.x*scl*gg.x, v.y*scl*gg.y, v.z*scl*gg.z, v.w*scl*gg.w);
    ((float4*)(Y + (size_t)m*Cc))[lane] = o;
}

// ---------------- per-row sort + drop-softmax ----------------
__global__ void sort_k(const float* __restrict__ sc, int* __restrict__ keep,
                       int* __restrict__ drop, float* __restrict__ phn){
    int r = blockIdx.x*blockDim.x + threadIdx.x;
    if (r >= NT) return;
    float s[Jn]; int id[Jn];
    #pragma unroll
    for (int j=0;j<Jn;j++){ s[j]=sc[r*Jn+j]; id[j]=j; }
    for (int i=1;i<Jn;i++){
        float sv=s[i]; int iv=id[i]; int p=i-1;
        while (p>=0 && s[p] < sv){ s[p+1]=s[p]; id[p+1]=id[p]; p--; }
        s[p+1]=sv; id[p+1]=iv;
    }
    #pragma unroll
    for (int p=0;p<KKEEP;p++) keep[r*KKEEP+p]=id[p];
    float mx = -1e30f;
    #pragma unroll
    for (int p=0;p<DDROP;p++) mx = fmaxf(mx, s[KKEEP+p]);
    float e[DDROP]; float sum=0.f;
    #pragma unroll
    for (int p=0;p<DDROP;p++){ e[p]=fast_exp(s[KKEEP+p]-mx); sum+=e[p]; }
    float inv = 1.f/sum;
    #pragma unroll
    for (int p=0;p<DDROP;p++){ drop[r*DDROP+p]=id[KKEEP+p]; phn[r*DDROP+p]=e[p]*inv; }
}

// ---------------- build x_slow ----------------
__global__ void build_slow_k(const float* __restrict__ xgcn, const float* __restrict__ cls,
                             const int* __restrict__ keep, const int* __restrict__ drop,
                             const float* __restrict__ phn, float* __restrict__ xslow){
    int nt = blockIdx.x; int c = threadIdx.x;
    size_t ob = (size_t)nt*LS*Cc;
    xslow[ob + c] = cls[c];
    #pragma unroll
    for (int p=0;p<KKEEP;p++){
        int j = keep[nt*KKEEP+p];
        xslow[ob + (size_t)(1+p)*Cc + c] = xgcn[((size_t)nt*Jn + j)*Cc + c];
    }
    float acc = 0.f;
    #pragma unroll
    for (int p=0;p<DDROP;p++){
        int j = drop[nt*DDROP+p];
        acc = fmaf(phn[nt*DDROP+p], xgcn[((size_t)nt*Jn + j)*Cc + c], acc);
    }
    xslow[ob + (size_t)(LS-1)*Cc + c] = acc;
}

// ---------------- spatial attention (L=19, 4 heads, warp per head) ----------------
__global__ void attn_s_k(const float* __restrict__ qkv, float* __restrict__ ao,
                         float* __restrict__ c2o){
    __shared__ float sq[NH][LS][HDIM];
    __shared__ float sv[NH][LS][HDIM];
    __shared__ float sp[NH][32];
    __shared__ float sc2[NH][LS-1];
    int nt = blockIdx.x; int tid = threadIdx.x; int h = tid>>5, lane = tid&31;
    const float* base = qkv + (size_t)nt*LS*384;
    for (int i=0;i<LS;i++){
        sq[h][i][lane] = base[i*384 + h*32 + lane]*0.176776695296637f; // 1/sqrt(32)
        sv[h][i][lane] = base[i*384 + 256 + h*32 + lane];
    }
    float4 kr[8];
    if (lane < LS){
        const float4* kp = (const float4*)(base + lane*384 + 128 + h*32);
        #pragma unroll
        for (int q=0;q<8;q++) kr[q]=kp[q];
    }
    __syncwarp();
    for (int i=0;i<LS;i++){
        float s = -1e30f;
        if (lane < LS){
            s = 0.f;
            const float4* qp = (const float4*)sq[h][i];
            #pragma unroll
            for (int q=0;q<8;q++){
                float4 a = qp[q];
                s = fmaf(a.x,kr[q].x,fmaf(a.y,kr[q].y,fmaf(a.z,kr[q].z,fmaf(a.w,kr[q].w,s))));
            }
        }
        float mx = wredmax(s);
        float e = (lane < LS) ? fast_exp(s-mx) : 0.f;
        float sum = wredsum(e);
        float p = e/sum;
        sp[h][lane] = p;
        __syncwarp();
        if (i==0 && lane>=1 && lane<LS) sc2[h][lane-1] = p;
        float o = 0.f;
        #pragma unroll
        for (int j=0;j<LS;j++) o = fmaf(sp[h][j], sv[h][j][lane], o);
        ao[((size_t)nt*LS + i)*Cc + h*32 + lane] = o;
        __syncwarp();
    }
    __syncthreads();
    if (tid < LS-1)
        c2o[(size_t)nt*(LS-1)+tid] = 0.25f*(sc2[0][tid]+sc2[1][tid]+sc2[2][tid]+sc2[3][tid]);
}

// ---------------- temporal attention (T=120, block = (seq, head)) ----------------
#define CHUNK 40
__global__ void attn_t_k(const float* __restrict__ qkv, float* __restrict__ ao){
    __shared__ float sq[CHUNK][HDIM];
    __shared__ float sv[Tt][HDIM];
    __shared__ float sS[CHUNK][Tt];
    int seq = blockIdx.x; int h = blockIdx.y;
    int tid = threadIdx.x, w = tid>>5, lane = tid&31;
    const float* base = qkv + (size_t)seq*Tt*384;
    for (int idx=tid; idx<Tt*HDIM; idx+=128){
        int j = idx>>5, d = idx&31;
        sv[j][d] = base[j*384 + 256 + h*32 + d];
    }
    float4 kr[8];
    if (tid < Tt){
        const float4* kp = (const float4*)(base + tid*384 + 128 + h*32);
        #pragma unroll
        for (int q=0;q<8;q++) kr[q]=kp[q];
    }
    for (int ch=0; ch<Tt; ch+=CHUNK){
        __syncthreads();
        for (int idx=tid; idx<CHUNK*HDIM; idx+=128){
            int il = idx>>5, d = idx&31;
            sq[il][d] = base[(size_t)(ch+il)*384 + h*32 + d]*0.176776695296637f;
        }
        __syncthreads();
        if (tid < Tt){
            for (int il=0; il<CHUNK; il++){
                const float4* qp = (const float4*)sq[il];
                float s = 0.f;
                #pragma unroll
                for (int q=0;q<8;q++){
                    float4 a = qp[q];
                    s = fmaf(a.x,kr[q].x,fmaf(a.y,kr[q].y,fmaf(a.z,kr[q].z,fmaf(a.w,kr[q].w,s))));
                }
                sS[il][tid] = s;
            }
        }
        __syncthreads();
        for (int il=w; il<CHUNK; il+=4){
            float v0 = sS[il][lane], v1 = sS[il][lane+32], v2 = sS[il][lane+64];
            float v3 = (lane<24) ? sS[il][lane+96] : -1e30f;
            float mx = fmaxf(fmaxf(v0,v1), fmaxf(v2,v3));
            mx = wredmax(mx);
            float e0=fast_exp(v0-mx), e1=fast_exp(v1-mx), e2=fast_exp(v2-mx);
            float e3 = (lane<24)?fast_exp(v3-mx):0.f;
            float sm = wredsum(e0+e1+e2+e3);
            float inv = 1.f/sm;
            sS[il][lane]=e0*inv; sS[il][lane+32]=e1*inv; sS[il][lane+64]=e2*inv;
            if (lane<24) sS[il][lane+96]=e3*inv;
        }
        __syncthreads();
        int r0 = w*(CHUNK/4);
        #pragma unroll
        for (int g=0; g<CHUNK/4; g+=5){
            float acc[5] = {0.f,0.f,0.f,0.f,0.f};
            for (int j=0;j<Tt;j++){
                float vv = sv[j][lane];
                #pragma unroll
                for (int rr=0;rr<5;rr++) acc[rr] = fmaf(sS[r0+g+rr][j], vv, acc[rr]);
            }
            #pragma unroll
            for (int rr=0;rr<5;rr++)
                ao[((size_t)seq*Tt + ch + r0+g+rr)*Cc + h*32 + lane] = acc[rr];
        }
    }
}

// ---------------- spatial scatter + next_attn ----------------
__global__ void scatter_k(const float* __restrict__ xgcn, const float* __restrict__ xmsa,
                          const float* __restrict__ ffn, const float* __restrict__ attnout,
                          const int* __restrict__ keep, const int* __restrict__ drop,
                          const float* __restrict__ c2o, float* __restrict__ xsp,
                          float* __restrict__ nextattn){
    int nt = blockIdx.x; int c = threadIdx.x;
    size_t sb = (size_t)nt*LS*Cc;
    float rep = attnout[sb + (size_t)(LS-1)*Cc + c] + ffn[sb + (size_t)(LS-1)*Cc + c];
    #pragma unroll
    for (int p=0;p<KKEEP;p++){
        int j = keep[nt*KKEEP+p];
        size_t o = ((size_t)nt*Jn + j)*Cc + c;
        xsp[o] = xgcn[o] + xmsa[sb + (size_t)(1+p)*Cc + c] + ffn[sb + (size_t)(1+p)*Cc + c];
    }
    #pragma unroll
    for (int p=0;p<DDROP;p++){
        int j = drop[nt*DDROP+p];
        size_t o = ((size_t)nt*Jn + j)*Cc + c;
        xsp[o] = 2.f*xgcn[o] + rep;
    }
    if (c < KKEEP)
        nextattn[(size_t)nt*Jn + keep[nt*KKEEP+c]] = c2o[nt*(LS-1)+c];
    else if (c < Jn)
        nextattn[(size_t)nt*Jn + drop[nt*DDROP + (c-KKEEP)]] = c2o[nt*(LS-1)+KKEEP];
}

// ---------------- layernorm (temporal LN1) ----------------
__global__ void ln_k(const float* __restrict__ X, const float* __restrict__ w,
                     const float* __restrict__ b, float* __restrict__ Y){
    int m = blockIdx.x*4 + (threadIdx.x>>5);
    int lane = threadIdx.x&31;
    const float4* xp = (const float4*)(X + (size_t)m*Cc);
    float4 v = xp[lane];
    float mean = wredsum(v.x+v.y+v.z+v.w)*(1.0f/Cc);
    float d0=v.x-mean, d1=v.y-mean, d2=v.z-mean, d3=v.w-mean;
    float var = wredsum(d0*d0+d1*d1+d2*d2+d3*d3)*(1.0f/Cc);
    float inv = rsqrtf(var + 1e-5f);
    float4 wv = ((const float4*)w)[lane];
    float4 bv = ((const float4*)b)[lane];
    float4 o = make_float4(d0*inv*wv.x+bv.x, d1*inv*wv.y+bv.y, d2*inv*wv.z+bv.z, d3*inv*wv.w+bv.w);
    ((float4*)(Y + (size_t)m*Cc))[lane] = o;
}

// ---------------- final: LN2 + rmsnorm + transpose-back + residuals ----------------
__global__ void final_k(const float* __restrict__ Xi, const float* __restrict__ w,
                        const float* __restrict__ b, const float* __restrict__ tnw,
                        const float* __restrict__ xsp, const float* __restrict__ xin,
                        float* __restrict__ out){
    int m = blockIdx.x*4 + (threadIdx.x>>5);
    int lane = threadIdx.x&31;
    const float4* xp = (const float4*)(Xi + (size_t)m*Cc);
    float4 v = xp[lane];
    float mean = wredsum(v.x+v.y+v.z+v.w)*(1.0f/Cc);
    float d0=v.x-mean, d1=v.y-mean, d2=v.z-mean, d3=v.w-mean;
    float var = wredsum(d0*d0+d1*d1+d2*d2+d3*d3)*(1.0f/Cc);
    float inv = rsqrtf(var + 1e-5f);
    float4 wv = ((const float4*)w)[lane];
    float4 bv = ((const float4*)b)[lane];
    float z0 = d0*inv*wv.x+bv.x, z1 = d1*inv*wv.y+bv.y, z2 = d2*inv*wv.z+bv.z, z3 = d3*inv*wv.w+bv.w;
    float ss = wredsum(z0*z0+z1*z1+z2*z2+z3*z3);
    float rs = rsqrtf(ss*(1.0f/Cc) + 1e-6f);
    float4 tv = ((const float4*)tnw)[lane];
    z0 *= rs*tv.x; z1 *= rs*tv.y; z2 *= rs*tv.z; z3 *= rs*tv.w;
    int dst = remap_row(m);
    float4 a = ((const float4*)(xsp + (size_t)dst*Cc))[lane];
    float4 c = ((const float4*)(xin + (size_t)dst*Cc))[lane];
    float4 o = make_float4(z0+a.x+c.x, z1+a.y+c.y, z2+a.z+c.z, z3+a.w+c.w);
    ((float4*)(out + (size_t)dst*Cc))[lane] = o;
}

// ---------------- host launch ----------------
extern "C" void kernel_launch(void* const* d_in, const int* in_sizes, int n_in,
                              void* d_out, int out_size){
    const float* x      = (const float*)d_in[0];
    const float* scores = (const float*)d_in[1];
    const float* gcn_w  = (const float*)d_in[2];
    const float* gnw    = (const float*)d_in[3];
    const float* cls    = (const float*)d_in[4];
    const float* sn1w   = (const float*)d_in[5];
    const float* sn2w   = (const float*)d_in[6];
    const float* s_inw  = (const float*)d_in[7];
    const float* s_inb  = (const float*)d_in[8];
    const float* s_ow   = (const float*)d_in[9];
    const float* s_ob   = (const float*)d_in[10];
    const float* s_f1w  = (const float*)d_in[11];
    const float* s_f1b  = (const float*)d_in[12];
    const float* s_f2w  = (const float*)d_in[13];
    const float* s_f2b  = (const float*)d_in[14];
    const float* t_inw  = (const float*)d_in[15];
    const float* t_inb  = (const float*)d_in[16];
    const float* t_ow   = (const float*)d_in[17];
    const float* t_ob   = (const float*)d_in[18];
    const float* t_l1w  = (const float*)d_in[19];
    const float* t_l1b  = (const float*)d_in[20];
    const float* t_l2w  = (const float*)d_in[21];
    const float* t_l2b  = (const float*)d_in[22];
    const float* t_f1w  = (const float*)d_in[23];
    const float* t_f1b  = (const float*)d_in[24];
    const float* t_f2w  = (const float*)d_in[25];
    const float* t_f2b  = (const float*)d_in[26];
    const float* tnw    = (const float*)d_in[27];
    float* out = (float*)d_out;
    float* out_attn = out + ((size_t)out_size - (size_t)NT*Jn);

    float *A,*B,*Cq,*D,*E,*F,*G,*Hh,*Ii,*Jb,*Wt,*PHN,*C2O;
    int *KEEP,*DROP;
    cudaGetSymbolAddress((void**)&A,  g_A);
    cudaGetSymbolAddress((void**)&B,  g_B);
    cudaGetSymbolAddress((void**)&Cq, g_C);
    cudaGetSymbolAddress((void**)&D,  g_D);
    cudaGetSymbolAddress((void**)&E,  g_E);
    cudaGetSymbolAddress((void**)&F,  g_F);
    cudaGetSymbolAddress((void**)&G,  g_G);
    cudaGetSymbolAddress((void**)&Hh, g_H);
    cudaGetSymbolAddress((void**)&Ii, g_I);
    cudaGetSymbolAddress((void**)&Jb, g_J);
    cudaGetSymbolAddress((void**)&Wt, g_Wt);
    cudaGetSymbolAddress((void**)&KEEP, g_keep);
    cudaGetSymbolAddress((void**)&DROP, g_drop);
    cudaGetSymbolAddress((void**)&PHN, g_phn);
    cudaGetSymbolAddress((void**)&C2O, g_c2o);

    cudaFuncSetAttribute(tgemm<128,128,0,false,false,false>, cudaFuncAttributeMaxDynamicSharedMemorySize, TG_SMEM);
    cudaFuncSetAttribute(tgemm<128,384,0,true, false,false>, cudaFuncAttributeMaxDynamicSharedMemorySize, TG_SMEM);
    cudaFuncSetAttribute(tgemm<128,256,1,true, false,false>, cudaFuncAttributeMaxDynamicSharedMemorySize, TG_SMEM);
    cudaFuncSetAttribute(tgemm<128,256,1,false,false,false>, cudaFuncAttributeMaxDynamicSharedMemorySize, TG_SMEM);
    cudaFuncSetAttribute(tgemm<256,128,0,false,false,false>, cudaFuncAttributeMaxDynamicSharedMemorySize, TG_SMEM);
    cudaFuncSetAttribute(tgemm<128,384,0,false,true, false>, cudaFuncAttributeMaxDynamicSharedMemorySize, TG_SMEM);
    cudaFuncSetAttribute(tgemm<128,128,0,false,false,true >, cudaFuncAttributeMaxDynamicSharedMemorySize, TG_SMEM);

    // 1) transpose gcn_w[0]; 2) sort scores
    transpose_k<<<128,128>>>(gcn_w, Wt);
    sort_k<<<NT/128,128>>>(scores, KEEP, DROP, PHN);

    // 3) GCN: E = x @ W0^T ; then A = rmsnorm(E)*gnw
    tgemm<128,128,0,false,false,false><<<M_T/128,128,TG_SMEM>>>(x, Wt, nullptr, E, nullptr, nullptr, nullptr);
    rms_k<<<M_T/4,128>>>(E, gnw, A);

    // 4) build x_slow
    build_slow_k<<<NT,128>>>(A, cls, KEEP, DROP, PHN, Jb);

    // 5) spatial QKV = rmsnorm(x_slow, sn1) @ s_inw^T + b
    tgemm<128,384,0,true,false,false><<<M_SP/128,128,TG_SMEM>>>(Jb, s_inw, s_inb, Cq, nullptr, nullptr, sn1w);

    // 6) spatial attention -> D, C2O
    attn_s_k<<<NT,128>>>(Cq, D, C2O);

    // 7) out-proj: E = attn_out ; F = x_slow + attn_out (x_msa)
    tgemm<128,128,0,false,false,false><<<M_SP/128,128,TG_SMEM>>>(D, s_ow, s_ob, E, Jb, F, nullptr);

    // 8) FFN1: H = gelu(rmsnorm(x_msa, sn2) @ s_f1w^T + b)
    tgemm<128,256,1,true,false,false><<<M_SP/128,128,TG_SMEM>>>(F, s_f1w, s_f1b, Hh, nullptr, nullptr, sn2w);

    // 9) FFN2: G = H @ s_f2w^T + b
    tgemm<256,128,0,false,false,false><<<M_SP/128,128,TG_SMEM>>>(Hh, s_f2w, s_f2b, G, nullptr, nullptr, nullptr);

    // 10) scatter -> B (x_sp), next_attn
    scatter_k<<<NT,128>>>(A, F, G, E, KEEP, DROP, C2O, B, out_attn);

    // 11) temporal QKV (row-remapped transpose fused)
    tgemm<128,384,0,false,true,false><<<M_T/128,128,TG_SMEM>>>(B, t_inw, t_inb, Cq, nullptr, nullptr, nullptr);

    // 12) temporal attention -> D
    attn_t_k<<<dim3(Nb*Jn, NH), 128>>>(Cq, D);

    // 13) out-proj: F = xt + a  (residual remapped from x_sp)
    tgemm<128,128,0,false,false,true><<<M_T/128,128,TG_SMEM>>>(D, t_ow, t_ob, E, B, F, nullptr);

    // 14) LN1: G = layernorm(F)
    ln_k<<<M_T/4,128>>>(F, t_l1w, t_l1b, G);

    // 15) FFN1: H = gelu(G @ t_f1w^T + b)
    tgemm<128,256,1,false,false,false><<<M_T/128,128,TG_SMEM>>>(G, t_f1w, t_f1b, Hh, nullptr, nullptr, nullptr);

    // 16) FFN2: I = xt1 + (H @ t_f2w^T + b)
    tgemm<256,128,0,false,false,false><<<M_T/128,128,TG_SMEM>>>(Hh, t_f2w, t_f2b, E, G, Ii, nullptr);

    // 17) LN2 + rmsnorm + transpose back + residuals -> out
    final_k<<<M_T/4,128>>>(Ii, t_l2w, t_l2b, tnw, B, x, out);
}